// round 1
// baseline (speedup 1.0000x reference)
#include <cuda_runtime.h>

#define NLOC 4096
#define NNEI 120
#define NI   128
#define NH   4
#define TOK  8
#define PAD  129
#define RSQRT_ND 0.17677669529663687f  /* 1/sqrt(32) */
#define SHIFT 20.0f

// Folded weights, rebuilt every launch (deterministic).
__device__ float d_Wqk[4 * 128 * 128];    // [h][m][i]
__device__ float d_Wfold[512 * 128];      // [(h*128+j)][o]

__global__ void prep_kernel(const float* __restrict__ Wq,
                            const float* __restrict__ Wkv,
                            const float* __restrict__ Wh) {
    int idx = blockIdx.x * blockDim.x + threadIdx.x;
    if (idx < 65536) {
        // Wqk[h][m][i] = sum_d Wq[m, d*4+h] * Wkv[i, d*4+h]
        int h = idx >> 14;
        int m = (idx >> 7) & 127;
        int i = idx & 127;
        float acc = 0.f;
#pragma unroll
        for (int d = 0; d < 32; d++)
            acc = fmaf(Wq[m * 128 + d * 4 + h], Wkv[i * 640 + d * 4 + h], acc);
        d_Wqk[idx] = acc;
    } else {
        // Wfold[h*128+j][o] = sum_i Wkv[j, (32+i)*4+h] * Wh[h*128+i, o]
        int z = idx - 65536;
        int r = z >> 7;        // h*128 + j
        int o = z & 127;
        int h = r >> 7;
        int j = r & 127;
        float acc = 0.f;
#pragma unroll 8
        for (int i = 0; i < 128; i++)
            acc = fmaf(Wkv[j * 640 + (32 + i) * 4 + h], Wh[(h * 128 + i) * 128 + o], acc);
        d_Wfold[z] = acc;
    }
}

__global__ __launch_bounds__(256, 2)
void atten_kernel(const float* __restrict__ g1,
                  const float* __restrict__ gg1,
                  const float* __restrict__ sw,
                  const float* __restrict__ bh,
                  float* __restrict__ out) {
    extern __shared__ float s[];
    float* gg1s  = s;                       // NNEI*PAD = 15480
    float* g1s   = gg1s + NNEI * PAD;       // TOK*128  = 1024
    float* sws   = g1s + TOK * 128;         // TOK*120  = 960
    float* qes   = sws + TOK * NNEI;        // TOK*512  = 4096
    float* cs    = qes + TOK * 512;         // TOK*512  = 4096
    float* scP   = cs + TOK * 512;          // 1024 (score partials / out scratch)
    float* attnw = scP + 1024;              // 512

    const int tid = threadIdx.x;
    const int l0  = blockIdx.x * TOK;

    for (int idx = tid; idx < TOK * 128; idx += 256)
        g1s[idx] = g1[l0 * 128 + idx];
    for (int idx = tid; idx < TOK * NNEI; idx += 256)
        sws[idx] = sw[l0 * NNEI + idx];
    __syncthreads();

    // ---- qe[t][h][i] = g1[t] . Wqk[h][:,i], batched over 8 tokens per weight read ----
    {
        const int h0 = tid >> 7;             // 0..1
        const int i0 = tid & 127;
        const float* w0p = d_Wqk + h0 * 16384 + i0;
        const float* w1p = d_Wqk + (h0 + 2) * 16384 + i0;
        float a0[TOK], a1[TOK];
#pragma unroll
        for (int t = 0; t < TOK; t++) { a0[t] = 0.f; a1[t] = 0.f; }
        for (int m = 0; m < 128; m++) {
            float w0 = w0p[m * 128];
            float w1 = w1p[m * 128];
#pragma unroll
            for (int t = 0; t < TOK; t++) {
                float gv = g1s[t * 128 + m];
                a0[t] = fmaf(gv, w0, a0[t]);
                a1[t] = fmaf(gv, w1, a1[t]);
            }
        }
#pragma unroll
        for (int t = 0; t < TOK; t++) {
            qes[t * 512 + h0 * 128 + i0]       = a0[t];
            qes[t * 512 + (h0 + 2) * 128 + i0] = a1[t];
        }
    }

    const int lane = tid & 31;
    const int wid  = tid >> 5;

    for (int t = 0; t < TOK; t++) {
        __syncthreads();  // prior c-phase done before gg1s overwrite (and qes ready on t=0)

        // ---- load gg1 tile (120x128 f32) once; float4 global reads, padded smem ----
        const float4* gsrc = reinterpret_cast<const float4*>(gg1 + (size_t)(l0 + t) * (NNEI * NI));
        for (int q = tid; q < NNEI * NI / 4; q += 256) {
            float4 v = gsrc[q];
            int n  = q >> 5;
            int j4 = (q & 31) << 2;
            float* dst = gg1s + n * PAD + j4;
            dst[0] = v.x; dst[1] = v.y; dst[2] = v.z; dst[3] = v.w;
        }
        __syncthreads();

        // ---- scores[h][n] = gg1[n] . qe[h], split j-range over 2 halves (240 threads) ----
        if (tid < 240) {
            int n  = tid % 120;
            int hf = tid / 120;
            const float* gr = gg1s + n * PAD + hf * 64;
            const float* qe = qes + t * 512 + hf * 64;
            float a0 = 0.f, a1 = 0.f, a2 = 0.f, a3 = 0.f;
#pragma unroll 16
            for (int j = 0; j < 64; j++) {
                float g = gr[j];
                a0 = fmaf(g, qe[j],       a0);
                a1 = fmaf(g, qe[128 + j], a1);
                a2 = fmaf(g, qe[256 + j], a2);
                a3 = fmaf(g, qe[384 + j], a3);
            }
            float* sp = scP + hf * 512 + n;
            sp[0]   = a0;
            sp[128] = a1;
            sp[256] = a2;
            sp[384] = a3;
        }
        __syncthreads();

        // ---- softmax per head: warp wid handles head wid ----
        if (wid < 4) {
            float vv[4];
            float mx = -1e30f;
#pragma unroll
            for (int k = 0; k < 4; k++) {
                int n = lane + k * 32;
                if (n < NNEI) {
                    float sc = (scP[wid * 128 + n] + scP[512 + wid * 128 + n]) * RSQRT_ND;
                    sc = (sc + SHIFT) * sws[t * NNEI + n] - SHIFT;
                    vv[k] = sc;
                    mx = fmaxf(mx, sc);
                } else {
                    vv[k] = -1e30f;
                }
            }
#pragma unroll
            for (int o = 16; o; o >>= 1) mx = fmaxf(mx, __shfl_xor_sync(0xffffffffu, mx, o));
            float sum = 0.f;
#pragma unroll
            for (int k = 0; k < 4; k++) { vv[k] = __expf(vv[k] - mx); sum += vv[k]; }
#pragma unroll
            for (int o = 16; o; o >>= 1) sum += __shfl_xor_sync(0xffffffffu, sum, o);
            float inv = 1.f / sum;
#pragma unroll
            for (int k = 0; k < 4; k++) {
                int n = lane + k * 32;
                if (n < NNEI) attnw[wid * 128 + n] = vv[k] * inv * sws[t * NNEI + n];
            }
        }
        __syncthreads();

        // ---- c[h][j] = sum_n attnw[h][n] * gg1[n][j] ----
#pragma unroll
        for (int p = 0; p < 2; p++) {
            int idx = tid + p * 256;
            int h = idx >> 7, j = idx & 127;
            const float* aw = attnw + h * 128;
            float acc = 0.f;
#pragma unroll 8
            for (int n = 0; n < NNEI; n++)
                acc = fmaf(aw[n], gg1s[n * PAD + j], acc);
            cs[t * 512 + idx] = acc;
        }
    }
    __syncthreads();

    // ---- out[t][o] = bh[o] + sum_f cs[t][f] * Wfold[f][o], batched over 8 tokens ----
    {
        int o  = tid & 127;
        int hf = tid >> 7;
        float acc[TOK];
#pragma unroll
        for (int t = 0; t < TOK; t++) acc[t] = 0.f;
        const float* wp = d_Wfold + hf * 256 * 128 + o;
        for (int idx = 0; idx < 256; idx++) {
            float w = wp[idx * 128];
            int fi = hf * 256 + idx;
#pragma unroll
            for (int t = 0; t < TOK; t++)
                acc[t] = fmaf(cs[t * 512 + fi], w, acc[t]);
        }
        if (hf == 1) {
#pragma unroll
            for (int t = 0; t < TOK; t++) scP[t * 128 + o] = acc[t];
        }
        __syncthreads();
        if (hf == 0) {
            float b = bh[o];
#pragma unroll
            for (int t = 0; t < TOK; t++)
                out[(l0 + t) * 128 + o] = acc[t] + scP[t * 128 + o] + b;
        }
    }
}

extern "C" void kernel_launch(void* const* d_in, const int* in_sizes, int n_in,
                              void* d_out, int out_size) {
    const float* g1  = (const float*)d_in[0];
    const float* gg1 = (const float*)d_in[1];
    // d_in[2] = nlist_mask: redundant (sw == uniform * mask, so sw==0 wherever masked)
    const float* sw  = (const float*)d_in[3];
    const float* Wq  = (const float*)d_in[4];
    const float* Wkv = (const float*)d_in[5];
    const float* Wh  = (const float*)d_in[6];
    const float* bh  = (const float*)d_in[7];
    float* out = (float*)d_out;

    const int smem_floats = NNEI * PAD + TOK * 128 + TOK * NNEI + TOK * 512 * 2 + 1024 + 512;
    const size_t SMEM = (size_t)smem_floats * sizeof(float);  // ~106 KB

    cudaFuncSetAttribute((const void*)atten_kernel,
                         cudaFuncAttributeMaxDynamicSharedMemorySize, (int)SMEM);

    prep_kernel<<<512, 256>>>(Wq, Wkv, Wh);
    atten_kernel<<<NLOC / TOK, 256, SMEM>>>(g1, gg1, sw, bh, out);
}

// round 2
// speedup vs baseline: 1.1060x; 1.1060x over previous
#include <cuda_runtime.h>

typedef unsigned long long ull;

#define NLOC 4096
#define NNEI 120
#define TOK  8
#define PAD  132
#define RSQRT_ND 0.17677669529663687f  /* 1/sqrt(32) */
#define SHIFT 20.0f

// smem float offsets
#define GG   0                 // 120*132 = 15840 : gg1 tile
#define G1P  15840             // 1024 : g1 packed [m][t]
#define SWS  16864             // 960
#define QES  17824             // 4096 : [t][i][h]
#define CS   21920             // 4096 : [f][t]
#define SCP  26016             // 1920 : [qa][h][n]
#define AW   27936             // 512  : [n][h]
#define CP   28448             // 4096 : [nq][j][h]
#define OUTP 32544             // 4096 : [fq][t][o]
#define SMEMF 36640

// Folded weights, rebuilt every launch (deterministic).
__device__ float d_Wqk[4 * 128 * 128];    // [h][m][i]
__device__ float d_Wfold[512 * 128];      // [(h*128+j)][o]

__global__ void prep_kernel(const float* __restrict__ Wq,
                            const float* __restrict__ Wkv,
                            const float* __restrict__ Wh) {
    int idx = blockIdx.x * blockDim.x + threadIdx.x;
    if (idx < 65536) {
        // Wqk[h][m][i] = sum_d Wq[m, d*4+h] * Wkv[i, d*4+h]
        int h = idx >> 14;
        int m = (idx >> 7) & 127;
        int i = idx & 127;
        float acc = 0.f;
#pragma unroll
        for (int d = 0; d < 32; d++)
            acc = fmaf(Wq[m * 128 + d * 4 + h], Wkv[i * 640 + d * 4 + h], acc);
        d_Wqk[idx] = acc;
    } else {
        // Wfold[h*128+j][o] = sum_i Wkv[j, (32+i)*4+h] * Wh[h*128+i, o]
        int z = idx - 65536;
        int r = z >> 7;        // h*128 + j
        int o = z & 127;
        int h = r >> 7;
        int j = r & 127;
        float acc = 0.f;
#pragma unroll 8
        for (int i = 0; i < 128; i++)
            acc = fmaf(Wkv[j * 640 + (32 + i) * 4 + h], Wh[(h * 128 + i) * 128 + o], acc);
        d_Wfold[z] = acc;
    }
}

__device__ __forceinline__ ull pk2(float x, float y) {
    ull r; asm("mov.b64 %0, {%1, %2};" : "=l"(r) : "f"(x), "f"(y)); return r;
}
__device__ __forceinline__ void upk2(ull v, float& x, float& y) {
    asm("mov.b64 {%0, %1}, %2;" : "=f"(x), "=f"(y) : "l"(v));
}
__device__ __forceinline__ ull ffma2(ull a, ull b, ull c) {
    ull d; asm("fma.rn.f32x2 %0, %1, %2, %3;" : "=l"(d) : "l"(a), "l"(b), "l"(c)); return d;
}

__global__ __launch_bounds__(512, 1)
void atten_kernel(const float* __restrict__ g1,
                  const float* __restrict__ gg1,
                  const float* __restrict__ sw,
                  const float* __restrict__ bh,
                  float* __restrict__ out) {
    extern __shared__ float s[];
    const int tid  = threadIdx.x;
    const int lane = tid & 31;
    const int wrp  = tid >> 5;
    const int l0   = blockIdx.x * TOK;

    // ---- prefetch tile(t=0): warp w owns contiguous 4KB (rows w*8..w*8+7), lane covers cols lane*4 ----
    float4 r[8];
    if (tid < 480) {
        const float4* src = reinterpret_cast<const float4*>(gg1 + (size_t)l0 * 15360) + wrp * 256 + lane;
#pragma unroll
        for (int k = 0; k < 8; k++) r[k] = src[k * 32];
    }

    // ---- g1 packed [m][t], sw ----
    for (int idx = tid; idx < TOK * 128; idx += 512) {
        int t = idx >> 7, m = idx & 127;
        s[G1P + m * 8 + t] = g1[(l0 + t) * 128 + m];
    }
    for (int idx = tid; idx < TOK * NNEI; idx += 512)
        s[SWS + idx] = sw[l0 * NNEI + idx];
    __syncthreads();

    // ---- Q: qe[t][h][i] = g1[t] . Wqk[h][:,i]; token-pairs via f32x2 ----
    {
        int h = tid >> 7, i = tid & 127;
        const float* wb = d_Wqk + h * 16384 + i;
        ull a0 = 0, a1 = 0, a2 = 0, a3 = 0;
#pragma unroll 4
        for (int m = 0; m < 128; m++) {
            float w = wb[m * 128];
            ull w2 = pk2(w, w);
            const ull* gp = reinterpret_cast<const ull*>(s + G1P + m * 8);
            a0 = ffma2(w2, gp[0], a0);
            a1 = ffma2(w2, gp[1], a1);
            a2 = ffma2(w2, gp[2], a2);
            a3 = ffma2(w2, gp[3], a3);
        }
        float x, y;
        upk2(a0, x, y); s[QES + 0 * 512 + i * 4 + h] = x; s[QES + 1 * 512 + i * 4 + h] = y;
        upk2(a1, x, y); s[QES + 2 * 512 + i * 4 + h] = x; s[QES + 3 * 512 + i * 4 + h] = y;
        upk2(a2, x, y); s[QES + 4 * 512 + i * 4 + h] = x; s[QES + 5 * 512 + i * 4 + h] = y;
        upk2(a3, x, y); s[QES + 6 * 512 + i * 4 + h] = x; s[QES + 7 * 512 + i * 4 + h] = y;
    }

    for (int t = 0; t < TOK; t++) {
        __syncthreads();  // gg1s free (prev c-phase done); also orders Q/qes before S

        // ---- STS tile from regs (conflict-free .128) ----
        if (tid < 480) {
#pragma unroll
            for (int k = 0; k < 8; k++)
                *reinterpret_cast<float4*>(s + GG + (wrp * 8 + k) * PAD + lane * 4) = r[k];
        }
        __syncthreads();

        // ---- scores partials: thread (n, quarter qa): head-pairs via f32x2 ----
        if (tid < 480) {
            int n = tid % 120, qa = tid / 120;
            const float* grow = s + GG + n * PAD + qa * 32;
            const ull* qrow = reinterpret_cast<const ull*>(s + QES + t * 512 + qa * 128);
            ull s01 = 0, s23 = 0;
#pragma unroll
            for (int jq = 0; jq < 8; jq++) {
                float4 g4 = *reinterpret_cast<const float4*>(grow + jq * 4);
                ull g2;
                g2 = pk2(g4.x, g4.x);
                s01 = ffma2(g2, qrow[(jq * 4 + 0) * 2],     s01);
                s23 = ffma2(g2, qrow[(jq * 4 + 0) * 2 + 1], s23);
                g2 = pk2(g4.y, g4.y);
                s01 = ffma2(g2, qrow[(jq * 4 + 1) * 2],     s01);
                s23 = ffma2(g2, qrow[(jq * 4 + 1) * 2 + 1], s23);
                g2 = pk2(g4.z, g4.z);
                s01 = ffma2(g2, qrow[(jq * 4 + 2) * 2],     s01);
                s23 = ffma2(g2, qrow[(jq * 4 + 2) * 2 + 1], s23);
                g2 = pk2(g4.w, g4.w);
                s01 = ffma2(g2, qrow[(jq * 4 + 3) * 2],     s01);
                s23 = ffma2(g2, qrow[(jq * 4 + 3) * 2 + 1], s23);
            }
            float x, y;
            upk2(s01, x, y); s[SCP + qa * 480 + 0 * 120 + n] = x; s[SCP + qa * 480 + 1 * 120 + n] = y;
            upk2(s23, x, y); s[SCP + qa * 480 + 2 * 120 + n] = x; s[SCP + qa * 480 + 3 * 120 + n] = y;
        }
        __syncthreads();

        // ---- softmax: warp h handles head h ----
        if (wrp < 4) {
            int h = wrp;
            float vv[4];
            float mx = -1e30f;
#pragma unroll
            for (int k = 0; k < 4; k++) {
                int n = lane + k * 32;
                if (n < NNEI) {
                    float sc = s[SCP + 0 * 480 + h * 120 + n] + s[SCP + 1 * 480 + h * 120 + n]
                             + s[SCP + 2 * 480 + h * 120 + n] + s[SCP + 3 * 480 + h * 120 + n];
                    sc *= RSQRT_ND;
                    sc = (sc + SHIFT) * s[SWS + t * NNEI + n] - SHIFT;
                    vv[k] = sc;
                    mx = fmaxf(mx, sc);
                } else vv[k] = -1e30f;
            }
#pragma unroll
            for (int o = 16; o; o >>= 1) mx = fmaxf(mx, __shfl_xor_sync(0xffffffffu, mx, o));
            float sum = 0.f;
#pragma unroll
            for (int k = 0; k < 4; k++) { vv[k] = __expf(vv[k] - mx); sum += vv[k]; }
#pragma unroll
            for (int o = 16; o; o >>= 1) sum += __shfl_xor_sync(0xffffffffu, sum, o);
            float inv = 1.f / sum;
#pragma unroll
            for (int k = 0; k < 4; k++) {
                int n = lane + k * 32;
                if (n < NNEI) s[AW + n * 4 + h] = vv[k] * inv * s[SWS + t * NNEI + n];
            }
        }
        __syncthreads();

        // ---- prefetch next tile (latency hidden under c-phase) ----
        if (t < 7 && tid < 480) {
            const float4* src = reinterpret_cast<const float4*>(gg1 + (size_t)(l0 + t + 1) * 15360) + wrp * 256 + lane;
#pragma unroll
            for (int k = 0; k < 8; k++) r[k] = src[k * 32];
        }

        // ---- c partials: thread (j-pair j2, n-slice nq); tile element read ONCE, 4 head-accs ----
        {
            int j2 = tid & 63, nq = tid >> 6;
            ull aA0 = 0, aA1 = 0, aB0 = 0, aB1 = 0;
            int n0 = nq * 15;
#pragma unroll 5
            for (int ii = 0; ii < 15; ii++) {
                int n = n0 + ii;
                ull g = *reinterpret_cast<const ull*>(s + GG + n * PAD + j2 * 2);
                float gA, gB; upk2(g, gA, gB);
                const ull* awp = reinterpret_cast<const ull*>(s + AW + n * 4);
                ull w01 = awp[0], w23 = awp[1];
                ull gA2 = pk2(gA, gA), gB2 = pk2(gB, gB);
                aA0 = ffma2(gA2, w01, aA0); aA1 = ffma2(gA2, w23, aA1);
                aB0 = ffma2(gB2, w01, aB0); aB1 = ffma2(gB2, w23, aB1);
            }
            ull* cp = reinterpret_cast<ull*>(s + CP + nq * 512 + 8 * j2);
            cp[0] = aA0; cp[1] = aA1; cp[2] = aB0; cp[3] = aB1;
        }
        __syncthreads();

        // ---- reduce partials -> cs[f][t]  (thread: h fast for conflict-free reads) ----
        {
            int j = tid >> 2, h = tid & 3;
            float acc = 0.f;
#pragma unroll
            for (int nq = 0; nq < 8; nq++) acc += s[CP + nq * 512 + j * 4 + h];
            s[CS + (h * 128 + j) * 8 + t] = acc;
        }
    }
    __syncthreads();

    // ---- out GEMM: out[t] = bh + cs[t] @ Wfold; token-pairs via f32x2 ----
    {
        int o = tid & 127, fq = tid >> 7;
        ull a0 = 0, a1 = 0, a2 = 0, a3 = 0;
        const float* wp = d_Wfold + fq * 128 * 128 + o;
#pragma unroll 4
        for (int ff = 0; ff < 128; ff++) {
            float w = wp[ff * 128];
            ull w2 = pk2(w, w);
            const ull* cp = reinterpret_cast<const ull*>(s + CS + (fq * 128 + ff) * 8);
            a0 = ffma2(w2, cp[0], a0);
            a1 = ffma2(w2, cp[1], a1);
            a2 = ffma2(w2, cp[2], a2);
            a3 = ffma2(w2, cp[3], a3);
        }
        float x, y;
        upk2(a0, x, y); s[OUTP + fq * 1024 + 0 * 128 + o] = x; s[OUTP + fq * 1024 + 1 * 128 + o] = y;
        upk2(a1, x, y); s[OUTP + fq * 1024 + 2 * 128 + o] = x; s[OUTP + fq * 1024 + 3 * 128 + o] = y;
        upk2(a2, x, y); s[OUTP + fq * 1024 + 4 * 128 + o] = x; s[OUTP + fq * 1024 + 5 * 128 + o] = y;
        upk2(a3, x, y); s[OUTP + fq * 1024 + 6 * 128 + o] = x; s[OUTP + fq * 1024 + 7 * 128 + o] = y;
    }
    __syncthreads();
#pragma unroll
    for (int rr = 0; rr < 2; rr++) {
        int idx = tid + rr * 512;
        int t = idx >> 7, o = idx & 127;
        float v = bh[o];
#pragma unroll
        for (int fq = 0; fq < 4; fq++) v += s[OUTP + fq * 1024 + t * 128 + o];
        out[(size_t)(l0 + t) * 128 + o] = v;
    }
}

extern "C" void kernel_launch(void* const* d_in, const int* in_sizes, int n_in,
                              void* d_out, int out_size) {
    const float* g1  = (const float*)d_in[0];
    const float* gg1 = (const float*)d_in[1];
    // d_in[2] = nlist_mask: redundant (sw == uniform * mask)
    const float* sw  = (const float*)d_in[3];
    const float* Wq  = (const float*)d_in[4];
    const float* Wkv = (const float*)d_in[5];
    const float* Wh  = (const float*)d_in[6];
    const float* bh  = (const float*)d_in[7];
    float* out = (float*)d_out;

    const size_t SMEM = (size_t)SMEMF * sizeof(float);  // ~143 KB

    cudaFuncSetAttribute((const void*)atten_kernel,
                         cudaFuncAttributeMaxDynamicSharedMemorySize, (int)SMEM);

    prep_kernel<<<512, 256>>>(Wq, Wkv, Wh);
    atten_kernel<<<NLOC / TOK, 512, SMEM>>>(g1, gg1, sw, bh, out);
}